// round 2
// baseline (speedup 1.0000x reference)
#include <cuda_runtime.h>
#include <cuda_bf16.h>
#include <cstdint>

// Problem dims
#define NUM_C 1024
#define EMB   512
#define HID   512
#define BATCH 64
#define SEQ   512
#define M_ROWS (BATCH * SEQ)   // 32768

// ---------------------------------------------------------------------------
// Device scratch (allocation-free contract: __device__ globals)
// ---------------------------------------------------------------------------
__device__ float    g_xproj[(size_t)M_ROWS * HID];   // 64 MB: Wx x + bx + bh
__device__ float    g_hs   [(size_t)M_ROWS * HID];   // 64 MB: scan outputs
__device__ float    g_ht   [2][HID * BATCH];         // transposed h double buffer: [j][b]
__device__ unsigned g_bar  [8];                      // per-batch-group barriers

// ---------------------------------------------------------------------------
// init: zero h0 (transposed buffer 0) and barrier counters
// ---------------------------------------------------------------------------
__global__ void init_kernel() {
    int tid = threadIdx.x;
    for (int i = tid; i < HID * BATCH; i += 256) g_ht[0][i] = 0.0f;
    if (tid < 8) g_bar[tid] = 0u;
}

// ---------------------------------------------------------------------------
// xproj GEMM: out[m][n] = sum_e emb[idx[m]][e] * Wx_w[n][e] + Wx_b[n] + Wh_b[n]
// 128x128 tile, BK=8, 256 threads, 8x8 per thread.
// ---------------------------------------------------------------------------
__global__ __launch_bounds__(256, 2)
void xproj_kernel(const int* __restrict__ q, const int* __restrict__ r,
                  const float* __restrict__ emb,
                  const float* __restrict__ Wx_w,
                  const float* __restrict__ Wx_b,
                  const float* __restrict__ Wh_b) {
    __shared__ float As[8][128];
    __shared__ float Bs[8][128];
    __shared__ int   sidx[128];

    const int tid  = threadIdx.x;
    const int row0 = blockIdx.y * 128;
    const int col0 = blockIdx.x * 128;

    if (tid < 128) {
        int m = row0 + tid;
        sidx[tid] = q[m] + NUM_C * r[m];
    }
    __syncthreads();

    const int lr = tid >> 1;          // 0..127
    const int lc = (tid & 1) * 4;     // 0 or 4
    const int tx = tid & 15;
    const int ty = tid >> 4;

    const int arow = sidx[lr];

    const float* aptr = emb  + (size_t)arow        * EMB;
    const float* bptr = Wx_w + (size_t)(col0 + lr) * EMB;

    float acc[8][8];
#pragma unroll
    for (int i = 0; i < 8; i++)
#pragma unroll
        for (int j = 0; j < 8; j++) acc[i][j] = 0.0f;

    float4 pa = *(const float4*)(aptr + lc);
    float4 pb = *(const float4*)(bptr + lc);

    for (int k0 = 0; k0 < EMB; k0 += 8) {
        __syncthreads();
        As[lc + 0][lr] = pa.x; As[lc + 1][lr] = pa.y;
        As[lc + 2][lr] = pa.z; As[lc + 3][lr] = pa.w;
        Bs[lc + 0][lr] = pb.x; Bs[lc + 1][lr] = pb.y;
        Bs[lc + 2][lr] = pb.z; Bs[lc + 3][lr] = pb.w;
        __syncthreads();

        if (k0 + 8 < EMB) {
            pa = *(const float4*)(aptr + k0 + 8 + lc);
            pb = *(const float4*)(bptr + k0 + 8 + lc);
        }

#pragma unroll
        for (int k = 0; k < 8; k++) {
            float ra[8], rb[8];
#pragma unroll
            for (int i = 0; i < 8; i++) ra[i] = As[k][ty * 8 + i];
#pragma unroll
            for (int j = 0; j < 8; j++) rb[j] = Bs[k][tx * 8 + j];
#pragma unroll
            for (int i = 0; i < 8; i++)
#pragma unroll
                for (int j = 0; j < 8; j++) acc[i][j] += ra[i] * rb[j];
        }
    }

#pragma unroll
    for (int i = 0; i < 8; i++) {
        int m = row0 + ty * 8 + i;
        float* op = g_xproj + (size_t)m * HID + col0 + tx * 8;
#pragma unroll
        for (int j = 0; j < 8; j++) {
            int n = col0 + tx * 8 + j;
            op[j] = acc[i][j] + Wx_b[n] + Wh_b[n];
        }
    }
}

// ---------------------------------------------------------------------------
// Persistent scan kernel.
// Grid: 128 CTAs = 8 batch-slices (8 b each) x 16 col-slices (32 j each).
// Sync only among the 16 CTAs sharing a batch slice (independent groups).
// Wh column-slice resident in smem for all 512 steps.
// Threads: 256 = 32 j-lanes x 8 k-slices (64 k each); smem reduction.
// ---------------------------------------------------------------------------
#define SCAN_SMEM_FLOATS (512 * 33 + 512 * 12 + 2048)
#define SCAN_SMEM_BYTES  (SCAN_SMEM_FLOATS * 4)

__global__ __launch_bounds__(256, 1)
void scan_kernel(const float* __restrict__ Wh_w,
                 const float* __restrict__ tau) {
    extern __shared__ float smem[];
    float* sw   = smem;                  // [512][33]  Wh slice, [k][jl]
    float* shT  = smem + 512 * 33;       // [512][12]  h transposed, [k][b] (8 used)
    float* sred = shT  + 512 * 12;       // [8][8][32] partial sums [ks][b][jl]

    const int tid = threadIdx.x;
    const int bs  = blockIdx.x >> 4;     // 0..7  batch slice
    const int js  = blockIdx.x & 15;     // 0..15 col slice
    const int j0  = js * 32;
    const int b0  = bs * 8;

    // ---- load Wh slice into smem (once) ----
    {
        int jl = tid >> 3;               // 0..31
        int kb = (tid & 7) * 4;          // float4 within 32-chunk
        const float* wrow = Wh_w + (size_t)(j0 + jl) * HID;
#pragma unroll
        for (int p = 0; p < 16; p++) {
            int k4 = kb + p * 32;
            float4 wv = *(const float4*)(wrow + k4);
            sw[(k4 + 0) * 33 + jl] = wv.x;
            sw[(k4 + 1) * 33 + jl] = wv.y;
            sw[(k4 + 2) * 33 + jl] = wv.z;
            sw[(k4 + 3) * 33 + jl] = wv.w;
        }
    }

    const int jl  = tid & 31;            // compute lane (column)
    const int ks  = tid >> 5;            // k-slice (warp)
    const int b_o = tid >> 5;            // output phase: batch row
    const float itau = 1.0f / tau[j0 + jl];

    __syncthreads();

    for (int s = 0; s < SEQ; s++) {
        // ---- stage h (transposed [j][b]) from L2, bypass L1 ----
        const float* hsrc = g_ht[s & 1];
#pragma unroll
        for (int p = 0; p < 4; p++) {
            int fi   = tid + p * 256;    // 0..1023
            int krow = fi >> 1;
            int half = fi & 1;
            float4 hv = __ldcg((const float4*)(hsrc + krow * BATCH + b0 + half * 4));
            *(float4*)(shT + krow * 12 + half * 4) = hv;
        }
        __syncthreads();

        // ---- partial GEMM: acc[b] = sum_{k in slice} h[b,k] * Wh[j,k] ----
        float acc0 = 0.f, acc1 = 0.f, acc2 = 0.f, acc3 = 0.f;
        float acc4 = 0.f, acc5 = 0.f, acc6 = 0.f, acc7 = 0.f;
        const int kbase = ks * 64;
#pragma unroll 4
        for (int kk = 0; kk < 64; kk++) {
            int k = kbase + kk;
            float w  = sw[k * 33 + jl];
            float4 ha = *(const float4*)(shT + k * 12);
            float4 hb = *(const float4*)(shT + k * 12 + 4);
            acc0 += ha.x * w; acc1 += ha.y * w;
            acc2 += ha.z * w; acc3 += ha.w * w;
            acc4 += hb.x * w; acc5 += hb.y * w;
            acc6 += hb.z * w; acc7 += hb.w * w;
        }
        {
            float* rp = sred + ks * 256 + jl;
            rp[0 * 32] = acc0; rp[1 * 32] = acc1; rp[2 * 32] = acc2; rp[3 * 32] = acc3;
            rp[4 * 32] = acc4; rp[5 * 32] = acc5; rp[6 * 32] = acc6; rp[7 * 32] = acc7;
        }
        __syncthreads();

        // ---- reduce 8 k-slices, apply cell update ----
        float sum = 0.f;
#pragma unroll
        for (int k2 = 0; k2 < 8; k2++) sum += sred[k2 * 256 + b_o * 32 + jl];

        float xp   = g_xproj[((size_t)(b0 + b_o) * SEQ + s) * HID + j0 + jl];
        float z    = sum + xp;
        float th   = tanhf(z);
        float hold = shT[(j0 + jl) * 12 + b_o];
        float hn   = hold + (th - hold) * itau;

        g_hs[((size_t)(b0 + b_o) * SEQ + s) * HID + j0 + jl] = hn;
        __stcg(&g_ht[(s + 1) & 1][(j0 + jl) * BATCH + b0 + b_o], hn);

        // ---- group barrier (16 CTAs sharing this batch slice) ----
        __threadfence();
        __syncthreads();
        if (tid == 0 && s < SEQ - 1) {
            atomicAdd(&g_bar[bs], 1u);                 // single RMW: announce arrival
            unsigned target = 16u * (unsigned)(s + 1);
            // relaxed poll (no RMW storm) with light backoff
            const volatile unsigned* p = &g_bar[bs];
            while (*p < target) { __nanosleep(64); }
        }
        __syncthreads();
    }
}

// ---------------------------------------------------------------------------
// Output GEMM + sigmoid: y[m][c] = sigmoid(sum_h hs[m][h]*Wo_w[c][h] + Wo_b[c])
// ---------------------------------------------------------------------------
__global__ __launch_bounds__(256, 2)
void out_kernel(const float* __restrict__ Wo_w,
                const float* __restrict__ Wo_b,
                float* __restrict__ out) {
    __shared__ float As[8][128];
    __shared__ float Bs[8][128];

    const int tid  = threadIdx.x;
    const int row0 = blockIdx.y * 128;
    const int col0 = blockIdx.x * 128;

    const int lr = tid >> 1;
    const int lc = (tid & 1) * 4;
    const int tx = tid & 15;
    const int ty = tid >> 4;

    const float* aptr = g_hs + (size_t)(row0 + lr) * HID;
    const float* bptr = Wo_w + (size_t)(col0 + lr) * HID;

    float acc[8][8];
#pragma unroll
    for (int i = 0; i < 8; i++)
#pragma unroll
        for (int j = 0; j < 8; j++) acc[i][j] = 0.0f;

    float4 pa = *(const float4*)(aptr + lc);
    float4 pb = *(const float4*)(bptr + lc);

    for (int k0 = 0; k0 < HID; k0 += 8) {
        __syncthreads();
        As[lc + 0][lr] = pa.x; As[lc + 1][lr] = pa.y;
        As[lc + 2][lr] = pa.z; As[lc + 3][lr] = pa.w;
        Bs[lc + 0][lr] = pb.x; Bs[lc + 1][lr] = pb.y;
        Bs[lc + 2][lr] = pb.z; Bs[lc + 3][lr] = pb.w;
        __syncthreads();

        if (k0 + 8 < HID) {
            pa = *(const float4*)(aptr + k0 + 8 + lc);
            pb = *(const float4*)(bptr + k0 + 8 + lc);
        }

#pragma unroll
        for (int k = 0; k < 8; k++) {
            float ra[8], rb[8];
#pragma unroll
            for (int i = 0; i < 8; i++) ra[i] = As[k][ty * 8 + i];
#pragma unroll
            for (int j = 0; j < 8; j++) rb[j] = Bs[k][tx * 8 + j];
#pragma unroll
            for (int i = 0; i < 8; i++)
#pragma unroll
                for (int j = 0; j < 8; j++) acc[i][j] += ra[i] * rb[j];
        }
    }

#pragma unroll
    for (int i = 0; i < 8; i++) {
        int m = row0 + ty * 8 + i;
        float* op = out + (size_t)m * NUM_C + col0 + tx * 8;
#pragma unroll
        for (int j = 0; j < 8; j++) {
            int n = col0 + tx * 8 + j;
            float logit = acc[i][j] + Wo_b[n];
            op[j] = 1.0f / (1.0f + expf(-logit));
        }
    }
}

// ---------------------------------------------------------------------------
extern "C" void kernel_launch(void* const* d_in, const int* in_sizes, int n_in,
                              void* d_out, int out_size) {
    const int*   q    = (const int*)  d_in[0];
    const int*   r    = (const int*)  d_in[1];
    const float* emb  = (const float*)d_in[2];
    const float* Wh_w = (const float*)d_in[3];
    const float* Wh_b = (const float*)d_in[4];
    const float* Wx_w = (const float*)d_in[5];
    const float* Wx_b = (const float*)d_in[6];
    const float* tau  = (const float*)d_in[7];
    const float* Wo_w = (const float*)d_in[8];
    const float* Wo_b = (const float*)d_in[9];
    float*       out  = (float*)d_out;

    // idempotent, capture-legal (not a stream op)
    cudaFuncSetAttribute(scan_kernel,
                         cudaFuncAttributeMaxDynamicSharedMemorySize,
                         SCAN_SMEM_BYTES);

    // 1) input projection GEMM (gather fused)
    {
        dim3 grid(HID / 128, M_ROWS / 128);
        xproj_kernel<<<grid, 256>>>(q, r, emb, Wx_w, Wx_b, Wh_b);
    }
    // 2) zero h0 + barriers
    init_kernel<<<1, 256>>>();
    // 3) persistent scan (128 CTAs, all co-resident)
    scan_kernel<<<128, 256, SCAN_SMEM_BYTES>>>(Wh_w, tau);
    // 4) output GEMM + sigmoid
    {
        dim3 grid(NUM_C / 128, M_ROWS / 128);
        out_kernel<<<grid, 256>>>(Wo_w, Wo_b, out);
    }
}